// round 2
// baseline (speedup 1.0000x reference)
#include <cuda_runtime.h>
#include <cuda_bf16.h>
#include <cstddef>

// Problem constants
#define BATCH 4
#define SEQ 2048
#define DIM 1024
#define NHEAD 16
#define HDIM 64
#define ROWS (BATCH * SEQ)            // 8192
#define QKVDIM (3 * DIM)              // 3072

// ---------------- scratch (static device globals; no allocation) ----------------
__device__ float g_qkv[(size_t)ROWS * QKVDIM];              // [B*S, 3072]
__device__ float g_q[(size_t)BATCH * NHEAD * SEQ * HDIM];   // [B,H,S,D], pre-scaled by 1/8
__device__ float g_k[(size_t)BATCH * NHEAD * SEQ * HDIM];
__device__ float g_v[(size_t)BATCH * NHEAD * SEQ * HDIM];
__device__ float g_ctx[(size_t)ROWS * DIM];                 // [B*S, H*D]

// ---------------- generic NT SGEMM: C[m,n] = sum_k A[m,k]*B[n,k] + bias[n] ----------------
// BM=BN=64, BK=16, 256 threads, 4x4 micro-tile per thread.
__global__ void __launch_bounds__(256) gemm_nt_bias(
    const float* __restrict__ A, const float* __restrict__ B,
    const float* __restrict__ bias, float* __restrict__ C,
    int M, int N, int K)
{
    __shared__ float As[16][64];
    __shared__ float Bs[16][64];

    const int tid = threadIdx.x;
    const int tx = tid & 15;     // n micro index
    const int ty = tid >> 4;     // m micro index
    const int m0 = blockIdx.y * 64;
    const int n0 = blockIdx.x * 64;

    const int lr = tid >> 2;          // 0..63 (row within tile)
    const int lk = (tid & 3) << 2;    // 0,4,8,12

    const float* Ap = A + (size_t)(m0 + lr) * K + lk;
    const float* Bp = B + (size_t)(n0 + lr) * K + lk;

    float acc[4][4] = {};

    for (int k0 = 0; k0 < K; k0 += 16) {
        float4 av = *(const float4*)(Ap + k0);
        float4 bv = *(const float4*)(Bp + k0);
        As[lk + 0][lr] = av.x; As[lk + 1][lr] = av.y;
        As[lk + 2][lr] = av.z; As[lk + 3][lr] = av.w;
        Bs[lk + 0][lr] = bv.x; Bs[lk + 1][lr] = bv.y;
        Bs[lk + 2][lr] = bv.z; Bs[lk + 3][lr] = bv.w;
        __syncthreads();

        #pragma unroll
        for (int k = 0; k < 16; k++) {
            float4 a = *(const float4*)&As[k][ty * 4];
            float4 b = *(const float4*)&Bs[k][tx * 4];
            acc[0][0] += a.x * b.x; acc[0][1] += a.x * b.y;
            acc[0][2] += a.x * b.z; acc[0][3] += a.x * b.w;
            acc[1][0] += a.y * b.x; acc[1][1] += a.y * b.y;
            acc[1][2] += a.y * b.z; acc[1][3] += a.y * b.w;
            acc[2][0] += a.z * b.x; acc[2][1] += a.z * b.y;
            acc[2][2] += a.z * b.z; acc[2][3] += a.z * b.w;
            acc[3][0] += a.w * b.x; acc[3][1] += a.w * b.y;
            acc[3][2] += a.w * b.z; acc[3][3] += a.w * b.w;
        }
        __syncthreads();
    }

    float4 bb = *(const float4*)(bias + n0 + tx * 4);
    #pragma unroll
    for (int i = 0; i < 4; i++) {
        float* cp = C + (size_t)(m0 + ty * 4 + i) * N + n0 + tx * 4;
        float4 r;
        r.x = acc[i][0] + bb.x;
        r.y = acc[i][1] + bb.y;
        r.z = acc[i][2] + bb.z;
        r.w = acc[i][3] + bb.w;
        *(float4*)cp = r;
    }
}

// ---------------- RMSNorm + RoPE + transpose into [B,H,S,D] ----------------
// one warp per (b, s, h); each lane handles d = 2*lane, 2*lane+1
__global__ void __launch_bounds__(256) normrope_kernel(
    const float* __restrict__ cosb, const float* __restrict__ sinb,
    const float* __restrict__ qw, const float* __restrict__ kw)
{
    const int gwarp = (blockIdx.x * blockDim.x + threadIdx.x) >> 5;
    const int lane = threadIdx.x & 31;
    const int h = gwarp & 15;
    const int bs = gwarp >> 4;           // b*SEQ + s
    const int s = bs & (SEQ - 1);
    const int b = bs >> 11;

    const float* base = g_qkv + (size_t)bs * QKVDIM;
    float2 q = ((const float2*)(base + h * HDIM))[lane];
    float2 k = ((const float2*)(base + DIM + h * HDIM))[lane];
    float2 v = ((const float2*)(base + 2 * DIM + h * HDIM))[lane];

    // rms over D=64
    float qs = q.x * q.x + q.y * q.y;
    float ks = k.x * k.x + k.y * k.y;
    #pragma unroll
    for (int o = 16; o; o >>= 1) {
        qs += __shfl_xor_sync(0xffffffffu, qs, o);
        ks += __shfl_xor_sync(0xffffffffu, ks, o);
    }
    float qr = rsqrtf(qs * (1.0f / 64.0f) + 1e-6f);
    float kr = rsqrtf(ks * (1.0f / 64.0f) + 1e-6f);

    float2 w_q = ((const float2*)qw)[lane];
    float2 w_k = ((const float2*)kw)[lane];
    float qn0 = q.x * qr * w_q.x, qn1 = q.y * qr * w_q.y;
    float kn0 = k.x * kr * w_k.x, kn1 = k.y * kr * w_k.y;

    float2 c = ((const float2*)(cosb + s * HDIM))[lane];
    float2 sn = ((const float2*)(sinb + s * HDIM))[lane];

    // rotate_half: rot[2i] = -x[2i+1], rot[2i+1] = x[2i]
    float qo0 = qn0 * c.x - qn1 * sn.x;
    float qo1 = qn1 * c.y + qn0 * sn.y;
    float ko0 = kn0 * c.x - kn1 * sn.x;
    float ko1 = kn1 * c.y + kn0 * sn.y;

    const float scale = 0.125f;   // 1/sqrt(64), folded into Q
    size_t off = ((size_t)(b * NHEAD + h) * SEQ + s) * HDIM;
    ((float2*)(g_q + off))[lane] = make_float2(qo0 * scale, qo1 * scale);
    ((float2*)(g_k + off))[lane] = make_float2(ko0, ko1);
    ((float2*)(g_v + off))[lane] = v;
}

// ---------------- flash attention: 128 queries/block, 1 query/thread ----------------
// smem: sK[64][64], sV[64][64], sS[128][65]
__global__ void __launch_bounds__(128) attn_kernel(
    const float* __restrict__ Qg, const float* __restrict__ Kg,
    const float* __restrict__ Vg, float* __restrict__ ctx)
{
    extern __shared__ float sm[];
    float* sK = sm;                 // 4096 floats
    float* sV = sm + 4096;          // 4096 floats
    float* sS = sm + 8192;          // 128*65 floats

    const int tid = threadIdx.x;
    const int bh = blockIdx.y;      // 0..63
    const int q0 = blockIdx.x * 128;

    const size_t headoff = (size_t)bh * SEQ * HDIM;

    float4 qr[16];
    {
        const float4* qp = (const float4*)(Qg + headoff + (size_t)(q0 + tid) * HDIM);
        #pragma unroll
        for (int i = 0; i < 16; i++) qr[i] = qp[i];
    }

    float m = -1e30f, l = 0.0f;
    float acc[64];
    #pragma unroll
    for (int d = 0; d < 64; d++) acc[d] = 0.0f;

    for (int kt = 0; kt < SEQ; kt += 64) {
        // cooperative load of K,V tiles (4096 floats each; 8 float4 per thread)
        {
            const float4* kg = (const float4*)(Kg + headoff + (size_t)kt * HDIM);
            const float4* vg = (const float4*)(Vg + headoff + (size_t)kt * HDIM);
            float4* sK4 = (float4*)sK;
            float4* sV4 = (float4*)sV;
            #pragma unroll
            for (int i = 0; i < 8; i++) {
                sK4[tid + i * 128] = kg[tid + i * 128];
                sV4[tid + i * 128] = vg[tid + i * 128];
            }
        }
        __syncthreads();

        // scores for this tile
        float tmax = -1e30f;
        #pragma unroll 2
        for (int j = 0; j < 64; j++) {
            const float4* krow = (const float4*)(sK + j * 64);
            float s0 = 0.f, s1 = 0.f, s2 = 0.f, s3 = 0.f;
            #pragma unroll
            for (int i = 0; i < 16; i += 4) {
                float4 k0 = krow[i + 0], k1 = krow[i + 1], k2 = krow[i + 2], k3 = krow[i + 3];
                s0 += qr[i + 0].x * k0.x + qr[i + 0].y * k0.y + qr[i + 0].z * k0.z + qr[i + 0].w * k0.w;
                s1 += qr[i + 1].x * k1.x + qr[i + 1].y * k1.y + qr[i + 1].z * k1.z + qr[i + 1].w * k1.w;
                s2 += qr[i + 2].x * k2.x + qr[i + 2].y * k2.y + qr[i + 2].z * k2.z + qr[i + 2].w * k2.w;
                s3 += qr[i + 3].x * k3.x + qr[i + 3].y * k3.y + qr[i + 3].z * k3.z + qr[i + 3].w * k3.w;
            }
            float sv = (s0 + s1) + (s2 + s3);
            sS[tid * 65 + j] = sv;
            tmax = fmaxf(tmax, sv);
        }

        float newm = fmaxf(m, tmax);
        float corr = __expf(m - newm);
        m = newm;
        float lt = 0.0f;
        #pragma unroll
        for (int j = 0; j < 64; j++) {
            float p = __expf(sS[tid * 65 + j] - m);
            lt += p;
            sS[tid * 65 + j] = p;
        }
        l = l * corr + lt;
        #pragma unroll
        for (int d = 0; d < 64; d++) acc[d] *= corr;

        #pragma unroll 2
        for (int j = 0; j < 64; j++) {
            float p = sS[tid * 65 + j];
            const float4* vrow = (const float4*)(sV + j * 64);
            #pragma unroll
            for (int i = 0; i < 16; i++) {
                float4 v = vrow[i];
                acc[4 * i + 0] += p * v.x;
                acc[4 * i + 1] += p * v.y;
                acc[4 * i + 2] += p * v.z;
                acc[4 * i + 3] += p * v.w;
            }
        }
        __syncthreads();
    }

    const float inv = 1.0f / l;
    const int b = bh >> 4, h = bh & 15;
    float* op = ctx + (size_t)(b * SEQ + q0 + tid) * DIM + h * HDIM;
    #pragma unroll
    for (int i = 0; i < 16; i++) {
        float4 r;
        r.x = acc[4 * i + 0] * inv;
        r.y = acc[4 * i + 1] * inv;
        r.z = acc[4 * i + 2] * inv;
        r.w = acc[4 * i + 3] * inv;
        ((float4*)op)[i] = r;
    }
}

// ---------------- launch ----------------
extern "C" void kernel_launch(void* const* d_in, const int* in_sizes, int n_in,
                              void* d_out, int out_size)
{
    const float* x        = (const float*)d_in[0];
    const float* rope_cos = (const float*)d_in[1];
    const float* rope_sin = (const float*)d_in[2];
    const float* qkv_w    = (const float*)d_in[3];
    const float* qkv_b    = (const float*)d_in[4];
    const float* proj_w   = (const float*)d_in[5];
    const float* proj_b   = (const float*)d_in[6];
    const float* q_norm_w = (const float*)d_in[7];
    const float* k_norm_w = (const float*)d_in[8];
    float* out = (float*)d_out;

    float *p_qkv, *p_q, *p_k, *p_v, *p_ctx;
    cudaGetSymbolAddress((void**)&p_qkv, g_qkv);
    cudaGetSymbolAddress((void**)&p_q, g_q);
    cudaGetSymbolAddress((void**)&p_k, g_k);
    cudaGetSymbolAddress((void**)&p_v, g_v);
    cudaGetSymbolAddress((void**)&p_ctx, g_ctx);

    // 1) qkv = x @ qkv_w^T + qkv_b     [8192,3072]
    {
        dim3 grid(QKVDIM / 64, ROWS / 64);
        gemm_nt_bias<<<grid, 256>>>(x, qkv_w, qkv_b, p_qkv, ROWS, QKVDIM, DIM);
    }

    // 2) rmsnorm + rope + split/transpose to [B,H,S,D]
    {
        int warps = BATCH * SEQ * NHEAD;         // 131072
        normrope_kernel<<<warps * 32 / 256, 256>>>(rope_cos, rope_sin, q_norm_w, k_norm_w);
    }

    // 3) attention
    {
        size_t smem = (size_t)(4096 + 4096 + 128 * 65) * sizeof(float);  // 66048
        cudaFuncSetAttribute(attn_kernel, cudaFuncAttributeMaxDynamicSharedMemorySize, (int)smem);
        dim3 grid(SEQ / 128, BATCH * NHEAD);
        attn_kernel<<<grid, 128, smem>>>(p_q, p_k, p_v, p_ctx);
    }

    // 4) out = ctx @ proj_w^T + proj_b  [8192,1024]
    {
        dim3 grid(DIM / 64, ROWS / 64);
        gemm_nt_bias<<<grid, 256>>>(p_ctx, proj_w, proj_b, out, ROWS, DIM, DIM);
    }
}

// round 5
// speedup vs baseline: 3.6345x; 3.6345x over previous
#include <cuda_runtime.h>
#include <cstddef>
#include <cstdint>

// Problem constants
#define BATCH 4
#define SEQ 2048
#define DIM 1024
#define NHEAD 16
#define HDIM 64
#define ROWS (BATCH * SEQ)            // 8192
#define QKVDIM (3 * DIM)              // 3072

// ---------------- scratch (static device globals; no allocation) ----------------
__device__ float g_qkv[(size_t)ROWS * QKVDIM];
__device__ float g_q[(size_t)BATCH * NHEAD * SEQ * HDIM];   // [B,H,S,D], pre-scaled by 1/8
__device__ float g_k[(size_t)BATCH * NHEAD * SEQ * HDIM];
__device__ float g_v[(size_t)BATCH * NHEAD * SEQ * HDIM];
__device__ float g_ctx[(size_t)ROWS * DIM];

// ---------------- tf32 helpers ----------------
__device__ __forceinline__ uint32_t f2tf(float x) {
    uint32_t r;
    asm("cvt.rna.tf32.f32 %0, %1;" : "=r"(r) : "f"(x));
    return r;
}

// D += A(16x8) * B(8x8); tf32 inputs, fp32 accum.
__device__ __forceinline__ void mma8(float* c,
    uint32_t a0, uint32_t a1, uint32_t a2, uint32_t a3,
    uint32_t b0, uint32_t b1)
{
    asm volatile(
        "mma.sync.aligned.m16n8k8.row.col.f32.tf32.tf32.f32 "
        "{%0,%1,%2,%3},{%4,%5,%6,%7},{%8,%9},{%0,%1,%2,%3};\n"
        : "+f"(c[0]), "+f"(c[1]), "+f"(c[2]), "+f"(c[3])
        : "r"(a0), "r"(a1), "r"(a2), "r"(a3), "r"(b0), "r"(b1));
}

__device__ __forceinline__ void cp16(uint32_t dst, const void* src) {
    asm volatile("cp.async.cg.shared.global [%0], [%1], 16;\n" :: "r"(dst), "l"(src));
}
__device__ __forceinline__ void cp_commit() { asm volatile("cp.async.commit_group;\n"); }
template <int N> __device__ __forceinline__ void cp_wait() {
    asm volatile("cp.async.wait_group %0;\n" :: "n"(N));
}

// ============================================================================
// Tensor-core NT GEMM: C[m,n] = sum_k A[m,k]*B[n,k] + bias[n]
// BM=BN=128, BK=32; 256 threads = 8 warps (4m x 2n), warp tile 32x64.
// XOR-swizzled smem: word = row*32 + (k ^ (4*(row&7))) -> conflict-free
// both for STS.128 staging and scalar fragment LDS.
// ============================================================================
__global__ void __launch_bounds__(256, 2) gemm_tc(
    const float* __restrict__ A, const float* __restrict__ B,
    const float* __restrict__ bias, float* __restrict__ C,
    int M, int N, int K)
{
    __shared__ uint32_t sA[128 * 32];
    __shared__ uint32_t sB[128 * 32];

    const int tid = threadIdx.x;
    const int lane = tid & 31, warp = tid >> 5;
    const int g = lane >> 2, tg = lane & 3;
    const int wm = warp & 3, wn = warp >> 2;
    const int m0 = blockIdx.y * 128, n0 = blockIdx.x * 128;

    // staging: row = tid>>1 (0..127), cols (tid&1)*16 .. +15
    const int sr = tid >> 1;
    const int sc = (tid & 1) * 16;
    const float* Ap = A + (size_t)(m0 + sr) * K + sc;
    const float* Bp = B + (size_t)(n0 + sr) * K + sc;

    float4 ra[4], rb[4];
    float acc[2][8][4];
    #pragma unroll
    for (int i = 0; i < 2; i++)
        #pragma unroll
        for (int j = 0; j < 8; j++)
            #pragma unroll
            for (int v = 0; v < 4; v++) acc[i][j][v] = 0.0f;

    // prologue load
    #pragma unroll
    for (int i = 0; i < 4; i++) {
        ra[i] = *(const float4*)(Ap + 4 * i);
        rb[i] = *(const float4*)(Bp + 4 * i);
    }

    const int swz = 4 * (sr & 7);

    for (int kb = 0; kb < K; kb += 32) {
        // store staged regs (converted to tf32) into swizzled smem
        #pragma unroll
        for (int i = 0; i < 4; i++) {
            int cx = (sc + 4 * i) ^ swz;
            uint4 va = make_uint4(f2tf(ra[i].x), f2tf(ra[i].y), f2tf(ra[i].z), f2tf(ra[i].w));
            uint4 vb = make_uint4(f2tf(rb[i].x), f2tf(rb[i].y), f2tf(rb[i].z), f2tf(rb[i].w));
            *(uint4*)&sA[sr * 32 + cx] = va;
            *(uint4*)&sB[sr * 32 + cx] = vb;
        }
        __syncthreads();

        if (kb + 32 < K) {
            #pragma unroll
            for (int i = 0; i < 4; i++) {
                ra[i] = *(const float4*)(Ap + kb + 32 + 4 * i);
                rb[i] = *(const float4*)(Bp + kb + 32 + 4 * i);
            }
        }

        #pragma unroll
        for (int ks = 0; ks < 4; ks++) {
            const int k = ks * 8 + tg;
            uint32_t af[2][4];
            #pragma unroll
            for (int mf = 0; mf < 2; mf++) {
                int r  = wm * 32 + mf * 16 + g;
                int r2 = r + 8;
                af[mf][0] = sA[r  * 32 + (k       ^ (4 * (r  & 7)))];
                af[mf][1] = sA[r2 * 32 + (k       ^ (4 * (r2 & 7)))];
                af[mf][2] = sA[r  * 32 + ((k + 4) ^ (4 * (r  & 7)))];
                af[mf][3] = sA[r2 * 32 + ((k + 4) ^ (4 * (r2 & 7)))];
            }
            #pragma unroll
            for (int nt = 0; nt < 8; nt++) {
                int n = wn * 64 + nt * 8 + g;
                uint32_t b0 = sB[n * 32 + (k       ^ (4 * (n & 7)))];
                uint32_t b1 = sB[n * 32 + ((k + 4) ^ (4 * (n & 7)))];
                mma8(acc[0][nt], af[0][0], af[0][1], af[0][2], af[0][3], b0, b1);
                mma8(acc[1][nt], af[1][0], af[1][1], af[1][2], af[1][3], b0, b1);
            }
        }
        __syncthreads();
    }

    // epilogue: bias + store
    #pragma unroll
    for (int mf = 0; mf < 2; mf++) {
        int r = m0 + wm * 32 + mf * 16 + g;
        #pragma unroll
        for (int nt = 0; nt < 8; nt++) {
            int col = n0 + wn * 64 + nt * 8 + 2 * tg;
            float2 bb = *(const float2*)(bias + col);
            float2 v0, v1;
            v0.x = acc[mf][nt][0] + bb.x; v0.y = acc[mf][nt][1] + bb.y;
            v1.x = acc[mf][nt][2] + bb.x; v1.y = acc[mf][nt][3] + bb.y;
            *(float2*)(C + (size_t)r * N + col)       = v0;
            *(float2*)(C + (size_t)(r + 8) * N + col) = v1;
        }
    }
}

// ---------------- RMSNorm + RoPE + transpose into [B,H,S,D] (unchanged) ----------------
__global__ void __launch_bounds__(256) normrope_kernel(
    const float* __restrict__ cosb, const float* __restrict__ sinb,
    const float* __restrict__ qw, const float* __restrict__ kw)
{
    const int gwarp = (blockIdx.x * blockDim.x + threadIdx.x) >> 5;
    const int lane = threadIdx.x & 31;
    const int h = gwarp & 15;
    const int bs = gwarp >> 4;
    const int s = bs & (SEQ - 1);
    const int b = bs >> 11;

    const float* base = g_qkv + (size_t)bs * QKVDIM;
    float2 q = ((const float2*)(base + h * HDIM))[lane];
    float2 k = ((const float2*)(base + DIM + h * HDIM))[lane];
    float2 v = ((const float2*)(base + 2 * DIM + h * HDIM))[lane];

    float qs = q.x * q.x + q.y * q.y;
    float ks = k.x * k.x + k.y * k.y;
    #pragma unroll
    for (int o = 16; o; o >>= 1) {
        qs += __shfl_xor_sync(0xffffffffu, qs, o);
        ks += __shfl_xor_sync(0xffffffffu, ks, o);
    }
    float qr = rsqrtf(qs * (1.0f / 64.0f) + 1e-6f);
    float kr = rsqrtf(ks * (1.0f / 64.0f) + 1e-6f);

    float2 w_q = ((const float2*)qw)[lane];
    float2 w_k = ((const float2*)kw)[lane];
    float qn0 = q.x * qr * w_q.x, qn1 = q.y * qr * w_q.y;
    float kn0 = k.x * kr * w_k.x, kn1 = k.y * kr * w_k.y;

    float2 c = ((const float2*)(cosb + s * HDIM))[lane];
    float2 sn = ((const float2*)(sinb + s * HDIM))[lane];

    float qo0 = qn0 * c.x - qn1 * sn.x;
    float qo1 = qn1 * c.y + qn0 * sn.y;
    float ko0 = kn0 * c.x - kn1 * sn.x;
    float ko1 = kn1 * c.y + kn0 * sn.y;

    const float scale = 0.125f;
    size_t off = ((size_t)(b * NHEAD + h) * SEQ + s) * HDIM;
    ((float2*)(g_q + off))[lane] = make_float2(qo0 * scale, qo1 * scale);
    ((float2*)(g_k + off))[lane] = make_float2(ko0, ko1);
    ((float2*)(g_v + off))[lane] = v;
}

// ============================================================================
// Tensor-core flash attention.
// Block: 128 queries x full head (D=64); 256 threads = 8 warps, 16 q-rows/warp.
// Q fragments live in registers (pre-scaled, tf32). K/V double-buffered via
// cp.async (raw fp32 bits -> truncated tf32 in the mma). Per-warp-private P
// strip in smem (only __syncwarp between P store and PV mma).
// ============================================================================
#define KLD 68
#define VLD 72
#define PLD 68
#define OFF_K0 0
#define OFF_V0 (2 * 64 * KLD)
#define OFF_P  (OFF_V0 + 2 * 64 * VLD)
#define SM_FLOATS (OFF_P + 128 * PLD)     // 26624 floats = 106496 bytes

__global__ void __launch_bounds__(256, 2) attn_tc(
    const float* __restrict__ Qg, const float* __restrict__ Kg,
    const float* __restrict__ Vg, float* __restrict__ ctx)
{
    extern __shared__ float sm[];
    const int tid = threadIdx.x;
    const int lane = tid & 31, w = tid >> 5;
    const int g = lane >> 2, tg = lane & 3;
    const int bh = blockIdx.y;
    const int q0 = blockIdx.x * 128;
    const size_t hoff = (size_t)bh * SEQ * HDIM;
    const uint32_t smb = (uint32_t)__cvta_generic_to_shared(sm);

    // Q fragments (A-operand) in registers
    uint32_t qa[8][4];
    {
        const float* Qp = Qg + hoff + (size_t)(q0 + w * 16) * HDIM;
        #pragma unroll
        for (int ks = 0; ks < 8; ks++) {
            qa[ks][0] = f2tf(Qp[(size_t)g * 64       + ks * 8 + tg]);
            qa[ks][1] = f2tf(Qp[(size_t)(g + 8) * 64 + ks * 8 + tg]);
            qa[ks][2] = f2tf(Qp[(size_t)g * 64       + ks * 8 + tg + 4]);
            qa[ks][3] = f2tf(Qp[(size_t)(g + 8) * 64 + ks * 8 + tg + 4]);
        }
    }

    float o[8][4];
    #pragma unroll
    for (int nt = 0; nt < 8; nt++)
        #pragma unroll
        for (int v = 0; v < 4; v++) o[nt][v] = 0.0f;
    float m0v = -1e30f, m1v = -1e30f, l0 = 0.0f, l1 = 0.0f;

    // stage one 64-key tile (K and V) into buffer `buf` via cp.async
    auto stage = [&](int kt, int buf) {
        const float* Ks = Kg + hoff + (size_t)kt * HDIM;
        const float* Vs = Vg + hoff + (size_t)kt * HDIM;
        #pragma unroll
        for (int j = 0; j < 4; j++) {
            int idx = tid + 256 * j;          // 16B chunk id, 0..1023
            int r = idx >> 4, c = (idx & 15) * 4;
            cp16(smb + (uint32_t)(OFF_K0 + buf * 64 * KLD + r * KLD + c) * 4, Ks + idx * 4);
            cp16(smb + (uint32_t)(OFF_V0 + buf * 64 * VLD + r * VLD + c) * 4, Vs + idx * 4);
        }
        cp_commit();
    };

    stage(0, 0);

    for (int t = 0; t < SEQ / 64; t++) {
        const int cur = t & 1;
        if (t + 1 < SEQ / 64) { stage((t + 1) * 64, 1 - cur); cp_wait<1>(); }
        else                  { cp_wait<0>(); }
        __syncthreads();

        const float* sK = sm + OFF_K0 + cur * 64 * KLD;
        const float* sV = sm + OFF_V0 + cur * 64 * VLD;
        float* sP = sm + OFF_P;

        // S = Q @ K^T  (16x64 per warp)
        float s[8][4];
        #pragma unroll
        for (int nt = 0; nt < 8; nt++)
            #pragma unroll
            for (int v = 0; v < 4; v++) s[nt][v] = 0.0f;

        #pragma unroll
        for (int ks = 0; ks < 8; ks++) {
            #pragma unroll
            for (int nt = 0; nt < 8; nt++) {
                uint32_t b0 = __float_as_uint(sK[(nt * 8 + g) * KLD + ks * 8 + tg]);
                uint32_t b1 = __float_as_uint(sK[(nt * 8 + g) * KLD + ks * 8 + tg + 4]);
                mma8(s[nt], qa[ks][0], qa[ks][1], qa[ks][2], qa[ks][3], b0, b1);
            }
        }

        // online softmax (rows r0 = w*16+g, r1 = r0+8)
        float mx0 = -1e30f, mx1 = -1e30f;
        #pragma unroll
        for (int nt = 0; nt < 8; nt++) {
            mx0 = fmaxf(mx0, fmaxf(s[nt][0], s[nt][1]));
            mx1 = fmaxf(mx1, fmaxf(s[nt][2], s[nt][3]));
        }
        mx0 = fmaxf(mx0, __shfl_xor_sync(0xffffffffu, mx0, 1));
        mx0 = fmaxf(mx0, __shfl_xor_sync(0xffffffffu, mx0, 2));
        mx1 = fmaxf(mx1, __shfl_xor_sync(0xffffffffu, mx1, 1));
        mx1 = fmaxf(mx1, __shfl_xor_sync(0xffffffffu, mx1, 2));

        float nm0 = fmaxf(m0v, mx0), nm1 = fmaxf(m1v, mx1);
        float c0 = __expf(m0v - nm0), c1 = __expf(m1v - nm1);
        m0v = nm0; m1v = nm1;

        float ls0 = 0.0f, ls1 = 0.0f;
        const int pr0 = (w * 16 + g) * PLD + 2 * tg;
        const int pr1 = (w * 16 + g + 8) * PLD + 2 * tg;
        #pragma unroll
        for (int nt = 0; nt < 8; nt++) {
            float p0 = __expf(s[nt][0] - nm0);
            float p1 = __expf(s[nt][1] - nm0);
            float p2 = __expf(s[nt][2] - nm1);
            float p3 = __expf(s[nt][3] - nm1);
            ls0 += p0 + p1; ls1 += p2 + p3;
            *(uint2*)&sP[pr0 + nt * 8] = make_uint2(f2tf(p0), f2tf(p1));
            *(uint2*)&sP[pr1 + nt * 8] = make_uint2(f2tf(p2), f2tf(p3));
        }
        ls0 += __shfl_xor_sync(0xffffffffu, ls0, 1);
        ls0 += __shfl_xor_sync(0xffffffffu, ls0, 2);
        ls1 += __shfl_xor_sync(0xffffffffu, ls1, 1);
        ls1 += __shfl_xor_sync(0xffffffffu, ls1, 2);
        l0 = l0 * c0 + ls0;
        l1 = l1 * c1 + ls1;

        #pragma unroll
        for (int nt = 0; nt < 8; nt++) {
            o[nt][0] *= c0; o[nt][1] *= c0;
            o[nt][2] *= c1; o[nt][3] *= c1;
        }
        __syncwarp();   // P strip is warp-private; make stores visible to the warp

        // O += P @ V
        #pragma unroll
        for (int ks = 0; ks < 8; ks++) {
            uint32_t a0 = __float_as_uint(sP[(w * 16 + g) * PLD     + ks * 8 + tg]);
            uint32_t a1 = __float_as_uint(sP[(w * 16 + g + 8) * PLD + ks * 8 + tg]);
            uint32_t a2 = __float_as_uint(sP[(w * 16 + g) * PLD     + ks * 8 + tg + 4]);
            uint32_t a3 = __float_as_uint(sP[(w * 16 + g + 8) * PLD + ks * 8 + tg + 4]);
            #pragma unroll
            for (int nt = 0; nt < 8; nt++) {
                uint32_t b0 = __float_as_uint(sV[(ks * 8 + tg) * VLD     + nt * 8 + g]);
                uint32_t b1 = __float_as_uint(sV[(ks * 8 + tg + 4) * VLD + nt * 8 + g]);
                mma8(o[nt], a0, a1, a2, a3, b0, b1);
            }
        }
        __syncthreads();
    }

    // epilogue: normalize and scatter into ctx [B*S, DIM]
    const float i0 = 1.0f / l0, i1 = 1.0f / l1;
    const int b = bh >> 4, h = bh & 15;
    const int r0 = q0 + w * 16 + g;
    #pragma unroll
    for (int nt = 0; nt < 8; nt++) {
        int col = h * 64 + nt * 8 + 2 * tg;
        float2 v0, v1;
        v0.x = o[nt][0] * i0; v0.y = o[nt][1] * i0;
        v1.x = o[nt][2] * i1; v1.y = o[nt][3] * i1;
        *(float2*)(ctx + (size_t)(b * SEQ + r0) * DIM + col)     = v0;
        *(float2*)(ctx + (size_t)(b * SEQ + r0 + 8) * DIM + col) = v1;
    }
}

// ---------------- launch ----------------
extern "C" void kernel_launch(void* const* d_in, const int* in_sizes, int n_in,
                              void* d_out, int out_size)
{
    const float* x        = (const float*)d_in[0];
    const float* rope_cos = (const float*)d_in[1];
    const float* rope_sin = (const float*)d_in[2];
    const float* qkv_w    = (const float*)d_in[3];
    const float* qkv_b    = (const float*)d_in[4];
    const float* proj_w   = (const float*)d_in[5];
    const float* proj_b   = (const float*)d_in[6];
    // d_in[7], d_in[8]: q_norm_w, k_norm_w
    const float* q_norm_w = (const float*)d_in[7];
    const float* k_norm_w = (const float*)d_in[8];
    float* out = (float*)d_out;

    float *p_qkv, *p_q, *p_k, *p_v, *p_ctx;
    cudaGetSymbolAddress((void**)&p_qkv, g_qkv);
    cudaGetSymbolAddress((void**)&p_q, g_q);
    cudaGetSymbolAddress((void**)&p_k, g_k);
    cudaGetSymbolAddress((void**)&p_v, g_v);
    cudaGetSymbolAddress((void**)&p_ctx, g_ctx);

    // 1) qkv = x @ qkv_w^T + qkv_b
    {
        dim3 grid(QKVDIM / 128, ROWS / 128);
        gemm_tc<<<grid, 256>>>(x, qkv_w, qkv_b, p_qkv, ROWS, QKVDIM, DIM);
    }

    // 2) rmsnorm + rope + transpose
    {
        int warps = BATCH * SEQ * NHEAD;
        normrope_kernel<<<warps * 32 / 256, 256>>>(rope_cos, rope_sin, q_norm_w, k_norm_w);
    }

    // 3) attention (tensor-core flash)
    {
        size_t smem = (size_t)SM_FLOATS * sizeof(float);   // 106496 B
        cudaFuncSetAttribute(attn_tc, cudaFuncAttributeMaxDynamicSharedMemorySize, (int)smem);
        dim3 grid(SEQ / 128, BATCH * NHEAD);
        attn_tc<<<grid, 256, smem>>>(p_q, p_k, p_v, p_ctx);
    }

    // 4) out = ctx @ proj_w^T + proj_b
    {
        dim3 grid(DIM / 128, ROWS / 128);
        gemm_tc<<<grid, 256>>>(p_ctx, proj_w, proj_b, out, ROWS, DIM, DIM);
    }
}